// round 5
// baseline (speedup 1.0000x reference)
#include <cuda_runtime.h>
#include <cuda_bf16.h>
#include <cstdint>

#define NN 6144
#define IN_DIM 512
#define CHANNELS 4
#define C_DIM 64
#define FDIM 256          // CHANNELS * C_DIM
#define CAP 128           // max neighbors per row (mean ~31, sd ~5.5)

// -------- scratch (device globals; no allocation allowed) --------
// Row NN of the feats arrays is a permanent all-zero row (zero-init at module
// load, never written) used as the padding sentinel target.
__device__ float g_featsA[(size_t)(NN + 1) * FDIM];
__device__ float g_featsB[(size_t)(NN + 1) * FDIM];
__device__ int   g_ell[(size_t)NN * CAP + 64];
__device__ int   g_deg[NN];

#define FMA2(d, a, b, c) \
    asm("fma.rn.f32x2 %0, %1, %2, %3;" : "=l"(d) : "l"(a), "l"(b), "l"(c))
#define PACK2(d, x) \
    asm("mov.b64 %0, {%1, %2};" : "=l"(d) : "f"(x), "f"(x))
#define UNPACK2(lo, hi, s) \
    asm("mov.b64 {%0, %1}, %2;" : "=f"(lo), "=f"(hi) : "l"(s))

// ============================================================
// Kernel 1: dense adj -> ELL (order-preserving, deterministic)
// one warp per row, int4 loads + 4-ballot compaction.
// Rows padded to a multiple of 4 with sentinel NN; g_deg stores
// the PADDED degree so iterate needs no guards.
// ============================================================
__global__ __launch_bounds__(256) void build_ell_kernel(const int* __restrict__ adj) {
    int row = blockIdx.x * 8 + (threadIdx.x >> 5);
    int lane = threadIdx.x & 31;
    const int4* arow = (const int4*)(adj + (size_t)row * NN);
    unsigned lt = (1u << lane) - 1u;
    int total = 0;
    int* erow = g_ell + (size_t)row * CAP;
    for (int it = 0; it < NN / 128; it++) {
        int4 v = arow[it * 32 + lane];
        bool p0 = v.x > 0, p1 = v.y > 0, p2 = v.z > 0, p3 = v.w > 0;
        unsigned b0 = __ballot_sync(0xffffffffu, p0);
        unsigned b1 = __ballot_sync(0xffffffffu, p1);
        unsigned b2 = __ballot_sync(0xffffffffu, p2);
        unsigned b3 = __ballot_sync(0xffffffffu, p3);
        int basec = __popc(b0 & lt) + __popc(b1 & lt) + __popc(b2 & lt) + __popc(b3 & lt);
        int idx0 = it * 128 + lane * 4;
        int pos = total + basec;
        if (p0) { if (pos < CAP) erow[pos] = idx0; pos++; }
        if (p1) { if (pos < CAP) erow[pos] = idx0 + 1; pos++; }
        if (p2) { if (pos < CAP) erow[pos] = idx0 + 2; pos++; }
        if (p3) { if (pos < CAP) erow[pos] = idx0 + 3; }
        total += __popc(b0) + __popc(b1) + __popc(b2) + __popc(b3);
    }
    int tc = total < CAP ? total : CAP;
    int pad = (tc + 3) & ~3;                 // CAP is a multiple of 4
    if (lane < pad - tc) erow[tc + lane] = NN;  // sentinel -> zero row
    if (lane == 0) g_deg[row] = pad;
}

// ============================================================
// Kernel 2: feats0 = l2norm(features @ W + b), layout [n][c*64+k]
// 64x64 tile, BK=16; inner product via packed fma.rn.f32x2
// (2 FLOP per fma-pipe slot -> 2x the scalar FFMA roofline).
// ============================================================
__global__ __launch_bounds__(256) void project_kernel(const float* __restrict__ feat,
                                                      const float* __restrict__ W,
                                                      const float* __restrict__ bias) {
    __shared__ float sA[16][64];   // [d][row]
    __shared__ float sB[16][64];   // [d][k]
    __shared__ float s_scale[64];

    const int c  = blockIdx.y;
    const int n0 = blockIdx.x * 64;
    const int t  = threadIdx.x;
    const int tx = t & 15, ty = t >> 4;

    unsigned long long acc2[2][4];   // row-pairs (ty*4+2i, +1) x 4 cols
#pragma unroll
    for (int i = 0; i < 2; i++)
#pragma unroll
        for (int j = 0; j < 4; j++) acc2[i][j] = 0ull;

    const float* Wc = W + (size_t)c * IN_DIM * C_DIM;

    const int lrow = t >> 2, lseg = t & 3;   // A-tile loader mapping
    const int ld   = t >> 4, lks  = t & 15;  // B-tile loader mapping

    for (int d0 = 0; d0 < IN_DIM; d0 += 16) {
        float4 a = *(const float4*)(feat + (size_t)(n0 + lrow) * IN_DIM + d0 + lseg * 4);
        sA[lseg * 4 + 0][lrow] = a.x;
        sA[lseg * 4 + 1][lrow] = a.y;
        sA[lseg * 4 + 2][lrow] = a.z;
        sA[lseg * 4 + 3][lrow] = a.w;
        float4 bv = *(const float4*)(Wc + (size_t)(d0 + ld) * C_DIM + lks * 4);
        *(float4*)&sB[ld][lks * 4] = bv;
        __syncthreads();
#pragma unroll
        for (int d = 0; d < 16; d++) {
            unsigned long long ap0 = *(const unsigned long long*)&sA[d][ty * 4];
            unsigned long long ap1 = *(const unsigned long long*)&sA[d][ty * 4 + 2];
            float4 bv2 = *(const float4*)&sB[d][tx * 4];
            unsigned long long bp0, bp1, bp2, bp3;
            PACK2(bp0, bv2.x); PACK2(bp1, bv2.y); PACK2(bp2, bv2.z); PACK2(bp3, bv2.w);
            FMA2(acc2[0][0], ap0, bp0, acc2[0][0]);
            FMA2(acc2[0][1], ap0, bp1, acc2[0][1]);
            FMA2(acc2[0][2], ap0, bp2, acc2[0][2]);
            FMA2(acc2[0][3], ap0, bp3, acc2[0][3]);
            FMA2(acc2[1][0], ap1, bp0, acc2[1][0]);
            FMA2(acc2[1][1], ap1, bp1, acc2[1][1]);
            FMA2(acc2[1][2], ap1, bp2, acc2[1][2]);
            FMA2(acc2[1][3], ap1, bp3, acc2[1][3]);
        }
        __syncthreads();
    }

    // unpack to r[row 0..3][col 0..3]
    float r[4][4];
#pragma unroll
    for (int i = 0; i < 2; i++)
#pragma unroll
        for (int j = 0; j < 4; j++)
            UNPACK2(r[2 * i][j], r[2 * i + 1][j], acc2[i][j]);

    float4 bb4 = *(const float4*)(bias + c * C_DIM + tx * 4);
    float bb[4] = {bb4.x, bb4.y, bb4.z, bb4.w};
    float ss[4];
#pragma unroll
    for (int i = 0; i < 4; i++) {
        float s = 0.f;
#pragma unroll
        for (int j = 0; j < 4; j++) {
            r[i][j] += bb[j];
            s += r[i][j] * r[i][j];
        }
        ss[i] = s;
    }
#pragma unroll
    for (int off = 1; off < 16; off <<= 1)
#pragma unroll
        for (int i = 0; i < 4; i++) ss[i] += __shfl_xor_sync(0xffffffffu, ss[i], off);
    if (tx == 0) {
#pragma unroll
        for (int i = 0; i < 4; i++) s_scale[ty * 4 + i] = rsqrtf(fmaxf(ss[i], 1e-24f));
    }
    __syncthreads();
#pragma unroll
    for (int i = 0; i < 4; i++) {
        float s = s_scale[ty * 4 + i];
        float4 o = make_float4(r[i][0] * s, r[i][1] * s, r[i][2] * s, r[i][3] * s);
        *(float4*)(g_featsA + (size_t)(n0 + ty * 4 + i) * FDIM + c * C_DIM + tx * 4) = o;
    }
}

// ============================================================
// Kernel 3: one attention+aggregate+renorm iteration.
// Warp per node. Split-contiguous layout: lane owns elements
// [4l,4l+4) (channel l>>4) and [128+4l,+4) (channel 2+(l>>4)).
// Both loads per neighbor are 32-lane contiguous 512B (100%
// sectors). Degree pre-padded to x4 with zero-row sentinel ->
// no guards in the loop. 4-way neighbor ILP.
// ============================================================
__global__ __launch_bounds__(128, 8) void iterate_kernel(int pass, float* __restrict__ d_final) {
    const float* __restrict__ src = (pass == 1) ? g_featsB : g_featsA;
    float* __restrict__ dst = (pass == 0) ? g_featsB : (pass == 1) ? g_featsA : d_final;

    const int w = threadIdx.x >> 5, lane = threadIdx.x & 31;
    const int n = blockIdx.x * 4 + w;

    const float* xp = src + (size_t)n * FDIM + lane * 4;
    float4 xA = *(const float4*)xp;          // channel (lane>>4)
    float4 xB = *(const float4*)(xp + 128);  // channel 2+(lane>>4)
    float4 aA = make_float4(0.f, 0.f, 0.f, 0.f);
    float4 aB = make_float4(0.f, 0.f, 0.f, 0.f);

    const int dp = g_deg[n];                 // padded degree (multiple of 4)
    const int* erow = g_ell + (size_t)n * CAP;

    for (int i = 0; i < dp; i += 4) {
        int col[4];
#pragma unroll
        for (int j = 0; j < 4; j++) col[j] = __ldg(erow + i + j);

        float4 yA[4], yB[4];
#pragma unroll
        for (int j = 0; j < 4; j++) {
            const float* yp = src + (size_t)col[j] * FDIM + lane * 4;
            yA[j] = *(const float4*)yp;
            yB[j] = *(const float4*)(yp + 128);
        }

        float pA[4], pB[4];
#pragma unroll
        for (int j = 0; j < 4; j++) {
            pA[j] = xA.x * yA[j].x + xA.y * yA[j].y + xA.z * yA[j].z + xA.w * yA[j].w;
            pB[j] = xB.x * yB[j].x + xB.y * yB[j].y + xB.z * yB[j].z + xB.w * yB[j].w;
        }
        // reduce within 16-lane halves (each half = one channel per chunk)
#pragma unroll
        for (int off = 1; off <= 8; off <<= 1) {
#pragma unroll
            for (int j = 0; j < 4; j++) {
                pA[j] += __shfl_xor_sync(0xffffffffu, pA[j], off);
                pB[j] += __shfl_xor_sync(0xffffffffu, pB[j], off);
            }
        }
        // softmax across the 4 channels; |p| <= 1 so no max-shift
#pragma unroll
        for (int j = 0; j < 4; j++) {
            float eA = __expf(pA[j]);        // e[ch lane>>4]
            float eB = __expf(pB[j]);        // e[ch 2+(lane>>4)]
            float u = eA + eB;
            float tden = u + __shfl_xor_sync(0xffffffffu, u, 16);  // e0+e1+e2+e3
            float rcp = __fdividef(1.f, tden);
            float wA = eA * rcp, wB = eB * rcp;
            aA.x += wA * yA[j].x; aA.y += wA * yA[j].y;
            aA.z += wA * yA[j].z; aA.w += wA * yA[j].w;
            aB.x += wB * yB[j].x; aB.y += wB * yB[j].y;
            aB.z += wB * yB[j].z; aB.w += wB * yB[j].w;
        }
    }

    // self + aggregate, per-channel L2 norm (channel = 16-lane half per chunk)
    float4 vA = make_float4(xA.x + aA.x, xA.y + aA.y, xA.z + aA.z, xA.w + aA.w);
    float4 vB = make_float4(xB.x + aB.x, xB.y + aB.y, xB.z + aB.z, xB.w + aB.w);
    float sqA = vA.x * vA.x + vA.y * vA.y + vA.z * vA.z + vA.w * vA.w;
    float sqB = vB.x * vB.x + vB.y * vB.y + vB.z * vB.z + vB.w * vB.w;
#pragma unroll
    for (int off = 1; off <= 8; off <<= 1) {
        sqA += __shfl_xor_sync(0xffffffffu, sqA, off);
        sqB += __shfl_xor_sync(0xffffffffu, sqB, off);
    }
    float scA = rsqrtf(fmaxf(sqA, 1e-24f));
    float scB = rsqrtf(fmaxf(sqB, 1e-24f));
    float* dp_out = dst + (size_t)n * FDIM + lane * 4;
    *(float4*)dp_out         = make_float4(vA.x * scA, vA.y * scA, vA.z * scA, vA.w * scA);
    *(float4*)(dp_out + 128) = make_float4(vB.x * scB, vB.y * scB, vB.z * scB, vB.w * scB);
}

// ============================================================
extern "C" void kernel_launch(void* const* d_in, const int* in_sizes, int n_in,
                              void* d_out, int out_size) {
    const float* features = (const float*)d_in[0];   // [6144, 512]
    const int*   adj      = (const int*)d_in[1];     // [6144, 6144]
    const float* W        = (const float*)d_in[2];   // [4, 512, 64]
    const float* b        = (const float*)d_in[3];   // [4, 1, 64]
    float* out = (float*)d_out;                      // [6144, 256]

    build_ell_kernel<<<NN / 8, 256>>>(adj);
    project_kernel<<<dim3(NN / 64, CHANNELS), 256>>>(features, W, b);
    iterate_kernel<<<NN / 4, 128>>>(0, out);
    iterate_kernel<<<NN / 4, 128>>>(1, out);
    iterate_kernel<<<NN / 4, 128>>>(2, out);
}

// round 6
// speedup vs baseline: 1.0510x; 1.0510x over previous
#include <cuda_runtime.h>
#include <cuda_bf16.h>
#include <cstdint>

#define NN 6144
#define IN_DIM 512
#define CHANNELS 4
#define C_DIM 64
#define FDIM 256          // CHANNELS * C_DIM
#define CAP 128           // max neighbors per row (mean ~31, sd ~5.5)

#define BUILD_BLOCKS (NN / 8)        // 768
#define PROJ_BLOCKS  ((NN / 64) * 4) // 384

// -------- scratch (device globals; no allocation allowed) --------
// Row NN is a permanent all-zero row (zero-init, never written): the
// padding-sentinel target, so the neighbor loop needs no guards.
__device__ float g_featsA[(size_t)(NN + 1) * FDIM];
__device__ float g_featsB[(size_t)(NN + 1) * FDIM];
__device__ int   g_ell[(size_t)NN * CAP + 64];
__device__ int   g_deg[NN];

#define FMA2(d, a, b, c) \
    asm("fma.rn.f32x2 %0, %1, %2, %3;" : "=l"(d) : "l"(a), "l"(b), "l"(c))
#define PACK2(d, x) \
    asm("mov.b64 %0, {%1, %2};" : "=l"(d) : "f"(x), "f"(x))
#define UNPACK2(lo, hi, s) \
    asm("mov.b64 {%0, %1}, %2;" : "=f"(lo), "=f"(hi) : "l"(s))

// ============================================================
// Fused prep: blocks [0,768) build ELL; blocks [768,1152) project.
// Both paths are the round-5 kernels verbatim; fusion only buys
// concurrency between DRAM-bound build and FMA-bound project.
// ============================================================
__global__ __launch_bounds__(256) void prep_kernel(const int* __restrict__ adj,
                                                   const float* __restrict__ feat,
                                                   const float* __restrict__ W,
                                                   const float* __restrict__ bias) {
    __shared__ float sA[16][64];
    __shared__ float sB[16][64];
    __shared__ float s_scale[64];

    if (blockIdx.x < BUILD_BLOCKS) {
        // ---------- ELL build: warp/row, int4 + 4-ballot, sentinel pad ----------
        int row = blockIdx.x * 8 + (threadIdx.x >> 5);
        int lane = threadIdx.x & 31;
        const int4* arow = (const int4*)(adj + (size_t)row * NN);
        unsigned lt = (1u << lane) - 1u;
        int total = 0;
        int* erow = g_ell + (size_t)row * CAP;
        for (int it = 0; it < NN / 128; it++) {
            int4 v = arow[it * 32 + lane];
            bool p0 = v.x > 0, p1 = v.y > 0, p2 = v.z > 0, p3 = v.w > 0;
            unsigned b0 = __ballot_sync(0xffffffffu, p0);
            unsigned b1 = __ballot_sync(0xffffffffu, p1);
            unsigned b2 = __ballot_sync(0xffffffffu, p2);
            unsigned b3 = __ballot_sync(0xffffffffu, p3);
            int basec = __popc(b0 & lt) + __popc(b1 & lt) + __popc(b2 & lt) + __popc(b3 & lt);
            int idx0 = it * 128 + lane * 4;
            int pos = total + basec;
            if (p0) { if (pos < CAP) erow[pos] = idx0; pos++; }
            if (p1) { if (pos < CAP) erow[pos] = idx0 + 1; pos++; }
            if (p2) { if (pos < CAP) erow[pos] = idx0 + 2; pos++; }
            if (p3) { if (pos < CAP) erow[pos] = idx0 + 3; }
            total += __popc(b0) + __popc(b1) + __popc(b2) + __popc(b3);
        }
        int tc = total < CAP ? total : CAP;
        int pad = (tc + 3) & ~3;
        if (lane < pad - tc) erow[tc + lane] = NN;   // sentinel -> zero row
        if (lane == 0) g_deg[row] = pad;
        return;
    }

    // ---------- projection: 64x64 tile, BK=16, packed f32x2 FMA ----------
    const int pb = blockIdx.x - BUILD_BLOCKS;
    const int c  = pb & 3;
    const int n0 = (pb >> 2) * 64;
    const int t  = threadIdx.x;
    const int tx = t & 15, ty = t >> 4;

    unsigned long long acc2[2][4];
#pragma unroll
    for (int i = 0; i < 2; i++)
#pragma unroll
        for (int j = 0; j < 4; j++) acc2[i][j] = 0ull;

    const float* Wc = W + (size_t)c * IN_DIM * C_DIM;
    const int lrow = t >> 2, lseg = t & 3;
    const int ld   = t >> 4, lks  = t & 15;

    for (int d0 = 0; d0 < IN_DIM; d0 += 16) {
        float4 a = *(const float4*)(feat + (size_t)(n0 + lrow) * IN_DIM + d0 + lseg * 4);
        sA[lseg * 4 + 0][lrow] = a.x;
        sA[lseg * 4 + 1][lrow] = a.y;
        sA[lseg * 4 + 2][lrow] = a.z;
        sA[lseg * 4 + 3][lrow] = a.w;
        float4 bv = *(const float4*)(Wc + (size_t)(d0 + ld) * C_DIM + lks * 4);
        *(float4*)&sB[ld][lks * 4] = bv;
        __syncthreads();
#pragma unroll
        for (int d = 0; d < 16; d++) {
            unsigned long long ap0 = *(const unsigned long long*)&sA[d][ty * 4];
            unsigned long long ap1 = *(const unsigned long long*)&sA[d][ty * 4 + 2];
            float4 bv2 = *(const float4*)&sB[d][tx * 4];
            unsigned long long bp0, bp1, bp2, bp3;
            PACK2(bp0, bv2.x); PACK2(bp1, bv2.y); PACK2(bp2, bv2.z); PACK2(bp3, bv2.w);
            FMA2(acc2[0][0], ap0, bp0, acc2[0][0]);
            FMA2(acc2[0][1], ap0, bp1, acc2[0][1]);
            FMA2(acc2[0][2], ap0, bp2, acc2[0][2]);
            FMA2(acc2[0][3], ap0, bp3, acc2[0][3]);
            FMA2(acc2[1][0], ap1, bp0, acc2[1][0]);
            FMA2(acc2[1][1], ap1, bp1, acc2[1][1]);
            FMA2(acc2[1][2], ap1, bp2, acc2[1][2]);
            FMA2(acc2[1][3], ap1, bp3, acc2[1][3]);
        }
        __syncthreads();
    }

    float r[4][4];
#pragma unroll
    for (int i = 0; i < 2; i++)
#pragma unroll
        for (int j = 0; j < 4; j++)
            UNPACK2(r[2 * i][j], r[2 * i + 1][j], acc2[i][j]);

    float4 bb4 = *(const float4*)(bias + c * C_DIM + tx * 4);
    float bb[4] = {bb4.x, bb4.y, bb4.z, bb4.w};
    float ss[4];
#pragma unroll
    for (int i = 0; i < 4; i++) {
        float s = 0.f;
#pragma unroll
        for (int j = 0; j < 4; j++) {
            r[i][j] += bb[j];
            s += r[i][j] * r[i][j];
        }
        ss[i] = s;
    }
#pragma unroll
    for (int off = 1; off < 16; off <<= 1)
#pragma unroll
        for (int i = 0; i < 4; i++) ss[i] += __shfl_xor_sync(0xffffffffu, ss[i], off);
    if (tx == 0) {
#pragma unroll
        for (int i = 0; i < 4; i++) s_scale[ty * 4 + i] = rsqrtf(fmaxf(ss[i], 1e-24f));
    }
    __syncthreads();
#pragma unroll
    for (int i = 0; i < 4; i++) {
        float s = s_scale[ty * 4 + i];
        float4 o = make_float4(r[i][0] * s, r[i][1] * s, r[i][2] * s, r[i][3] * s);
        *(float4*)(g_featsA + (size_t)(n0 + ty * 4 + i) * FDIM + c * C_DIM + tx * 4) = o;
    }
}

// ============================================================
// Iterate: warp per node, lane owns floats [8l, 8l+8) (channel
// l>>3). 4 neighbors per trip, guard-free (sentinel-padded degree),
// uniform __ldg neighbor fetch, 5 shfls + 1 exp + 1 div per neighbor.
// ============================================================
__global__ __launch_bounds__(128) void iterate_kernel(int pass, float* __restrict__ d_final) {
    const float* __restrict__ src = (pass == 1) ? g_featsB : g_featsA;
    float* __restrict__ dst = (pass == 0) ? g_featsB : (pass == 1) ? g_featsA : d_final;

    const int w = threadIdx.x >> 5, lane = threadIdx.x & 31;
    const int n = blockIdx.x * 4 + w;

    const float* xrow = src + (size_t)n * FDIM + lane * 8;
    float4 x0 = *(const float4*)xrow;
    float4 x1 = *(const float4*)(xrow + 4);
    float4 a0 = make_float4(0.f, 0.f, 0.f, 0.f);
    float4 a1 = make_float4(0.f, 0.f, 0.f, 0.f);

    const int dp = g_deg[n];                 // padded to multiple of 4
    const int* erow = g_ell + (size_t)n * CAP;

    for (int i = 0; i < dp; i += 4) {
        int col[4];
#pragma unroll
        for (int j = 0; j < 4; j++) col[j] = __ldg(erow + i + j);   // uniform

        float4 y0[4], y1[4];
#pragma unroll
        for (int j = 0; j < 4; j++) {
            const float* yr = src + (size_t)col[j] * FDIM + lane * 8;
            y0[j] = *(const float4*)yr;
            y1[j] = *(const float4*)(yr + 4);
        }

        float p[4];
#pragma unroll
        for (int j = 0; j < 4; j++)
            p[j] = x0.x * y0[j].x + x0.y * y0[j].y + x0.z * y0[j].z + x0.w * y0[j].w +
                   x1.x * y1[j].x + x1.y * y1[j].y + x1.z * y1[j].z + x1.w * y1[j].w;
#pragma unroll
        for (int j = 0; j < 4; j++) p[j] += __shfl_xor_sync(0xffffffffu, p[j], 1);
#pragma unroll
        for (int j = 0; j < 4; j++) p[j] += __shfl_xor_sync(0xffffffffu, p[j], 2);
#pragma unroll
        for (int j = 0; j < 4; j++) p[j] += __shfl_xor_sync(0xffffffffu, p[j], 4);
        // |p| <= 1 (unit-norm channel rows): no max-shift needed
        float e[4], t[4];
#pragma unroll
        for (int j = 0; j < 4; j++) e[j] = __expf(p[j]);
#pragma unroll
        for (int j = 0; j < 4; j++) t[j] = e[j] + __shfl_xor_sync(0xffffffffu, e[j], 8);
#pragma unroll
        for (int j = 0; j < 4; j++) t[j] += __shfl_xor_sync(0xffffffffu, t[j], 16);
#pragma unroll
        for (int j = 0; j < 4; j++) {
            float wgt = __fdividef(e[j], t[j]);
            a0.x += wgt * y0[j].x; a0.y += wgt * y0[j].y;
            a0.z += wgt * y0[j].z; a0.w += wgt * y0[j].w;
            a1.x += wgt * y1[j].x; a1.y += wgt * y1[j].y;
            a1.z += wgt * y1[j].z; a1.w += wgt * y1[j].w;
        }
    }

    // self + aggregate, per-channel (8-lane group) L2 norm
    float v[8];
    v[0] = x0.x + a0.x; v[1] = x0.y + a0.y; v[2] = x0.z + a0.z; v[3] = x0.w + a0.w;
    v[4] = x1.x + a1.x; v[5] = x1.y + a1.y; v[6] = x1.z + a1.z; v[7] = x1.w + a1.w;
    float sq = 0.f;
#pragma unroll
    for (int k = 0; k < 8; k++) sq += v[k] * v[k];
    sq += __shfl_xor_sync(0xffffffffu, sq, 1);
    sq += __shfl_xor_sync(0xffffffffu, sq, 2);
    sq += __shfl_xor_sync(0xffffffffu, sq, 4);
    float sc = rsqrtf(fmaxf(sq, 1e-24f));
    float* drow = dst + (size_t)n * FDIM + lane * 8;
    *(float4*)drow       = make_float4(v[0] * sc, v[1] * sc, v[2] * sc, v[3] * sc);
    *(float4*)(drow + 4) = make_float4(v[4] * sc, v[5] * sc, v[6] * sc, v[7] * sc);
}

// ============================================================
extern "C" void kernel_launch(void* const* d_in, const int* in_sizes, int n_in,
                              void* d_out, int out_size) {
    const float* features = (const float*)d_in[0];   // [6144, 512]
    const int*   adj      = (const int*)d_in[1];     // [6144, 6144]
    const float* W        = (const float*)d_in[2];   // [4, 512, 64]
    const float* b        = (const float*)d_in[3];   // [4, 1, 64]
    float* out = (float*)d_out;                      // [6144, 256]

    prep_kernel<<<BUILD_BLOCKS + PROJ_BLOCKS, 256>>>(adj, features, W, b);
    iterate_kernel<<<NN / 4, 128>>>(0, out);
    iterate_kernel<<<NN / 4, 128>>>(1, out);
    iterate_kernel<<<NN / 4, 128>>>(2, out);
}

// round 8
// speedup vs baseline: 1.1109x; 1.0570x over previous
#include <cuda_runtime.h>
#include <cuda_bf16.h>
#include <cstdint>

#define NN 6144
#define IN_DIM 512
#define CHANNELS 4
#define C_DIM 64
#define FDIM 256          // CHANNELS * C_DIM
#define CAP 128           // max neighbors per row (mean ~31, sd ~5.5)

// -------- scratch (device globals; no allocation allowed) --------
// Row NN is a permanent all-zero row (zero-init, never written): the
// padding-sentinel target, so the neighbor loop needs no guards.
__device__ float g_featsA[(size_t)(NN + 1) * FDIM];
__device__ float g_featsB[(size_t)(NN + 1) * FDIM];
__device__ int   g_ell[(size_t)NN * CAP + 64];
__device__ int   g_deg[NN];

#define FMA2(d, a, b, c) \
    asm("fma.rn.f32x2 %0, %1, %2, %3;" : "=l"(d) : "l"(a), "l"(b), "l"(c))
#define PACK2(d, x) \
    asm("mov.b64 %0, {%1, %2};" : "=l"(d) : "f"(x), "f"(x))
#define UNPACK2(lo, hi, s) \
    asm("mov.b64 {%0, %1}, %2;" : "=f"(lo), "=f"(hi) : "l"(s))

// ============================================================
// Kernel 1: dense adj -> ELL (order-preserving, deterministic)
// warp/row, int4 + 4-ballot compaction, sentinel padding to x4.
// ============================================================
__global__ __launch_bounds__(256) void build_ell_kernel(const int* __restrict__ adj) {
    int row = blockIdx.x * 8 + (threadIdx.x >> 5);
    int lane = threadIdx.x & 31;
    const int4* arow = (const int4*)(adj + (size_t)row * NN);
    unsigned lt = (1u << lane) - 1u;
    int total = 0;
    int* erow = g_ell + (size_t)row * CAP;
    for (int it = 0; it < NN / 128; it++) {
        int4 v = arow[it * 32 + lane];
        bool p0 = v.x > 0, p1 = v.y > 0, p2 = v.z > 0, p3 = v.w > 0;
        unsigned b0 = __ballot_sync(0xffffffffu, p0);
        unsigned b1 = __ballot_sync(0xffffffffu, p1);
        unsigned b2 = __ballot_sync(0xffffffffu, p2);
        unsigned b3 = __ballot_sync(0xffffffffu, p3);
        int basec = __popc(b0 & lt) + __popc(b1 & lt) + __popc(b2 & lt) + __popc(b3 & lt);
        int idx0 = it * 128 + lane * 4;
        int pos = total + basec;
        if (p0) { if (pos < CAP) erow[pos] = idx0; pos++; }
        if (p1) { if (pos < CAP) erow[pos] = idx0 + 1; pos++; }
        if (p2) { if (pos < CAP) erow[pos] = idx0 + 2; pos++; }
        if (p3) { if (pos < CAP) erow[pos] = idx0 + 3; }
        total += __popc(b0) + __popc(b1) + __popc(b2) + __popc(b3);
    }
    int tc = total < CAP ? total : CAP;
    int pad = (tc + 3) & ~3;
    if (lane < pad - tc) erow[tc + lane] = NN;   // sentinel -> zero row
    if (lane == 0) g_deg[row] = pad;
}

// ============================================================
// Kernel 2: feats0 = l2norm(features @ W + b), layout [n][c*64+k]
// 64x64 tile, BK=16, packed fma.rn.f32x2 (round-5 version).
// ============================================================
__global__ __launch_bounds__(256) void project_kernel(const float* __restrict__ feat,
                                                      const float* __restrict__ W,
                                                      const float* __restrict__ bias) {
    __shared__ float sA[16][64];
    __shared__ float sB[16][64];
    __shared__ float s_scale[64];

    const int c  = blockIdx.y;
    const int n0 = blockIdx.x * 64;
    const int t  = threadIdx.x;
    const int tx = t & 15, ty = t >> 4;

    unsigned long long acc2[2][4];
#pragma unroll
    for (int i = 0; i < 2; i++)
#pragma unroll
        for (int j = 0; j < 4; j++) acc2[i][j] = 0ull;

    const float* Wc = W + (size_t)c * IN_DIM * C_DIM;
    const int lrow = t >> 2, lseg = t & 3;
    const int ld   = t >> 4, lks  = t & 15;

    for (int d0 = 0; d0 < IN_DIM; d0 += 16) {
        float4 a = *(const float4*)(feat + (size_t)(n0 + lrow) * IN_DIM + d0 + lseg * 4);
        sA[lseg * 4 + 0][lrow] = a.x;
        sA[lseg * 4 + 1][lrow] = a.y;
        sA[lseg * 4 + 2][lrow] = a.z;
        sA[lseg * 4 + 3][lrow] = a.w;
        float4 bv = *(const float4*)(Wc + (size_t)(d0 + ld) * C_DIM + lks * 4);
        *(float4*)&sB[ld][lks * 4] = bv;
        __syncthreads();
#pragma unroll
        for (int d = 0; d < 16; d++) {
            unsigned long long ap0 = *(const unsigned long long*)&sA[d][ty * 4];
            unsigned long long ap1 = *(const unsigned long long*)&sA[d][ty * 4 + 2];
            float4 bv2 = *(const float4*)&sB[d][tx * 4];
            unsigned long long bp0, bp1, bp2, bp3;
            PACK2(bp0, bv2.x); PACK2(bp1, bv2.y); PACK2(bp2, bv2.z); PACK2(bp3, bv2.w);
            FMA2(acc2[0][0], ap0, bp0, acc2[0][0]);
            FMA2(acc2[0][1], ap0, bp1, acc2[0][1]);
            FMA2(acc2[0][2], ap0, bp2, acc2[0][2]);
            FMA2(acc2[0][3], ap0, bp3, acc2[0][3]);
            FMA2(acc2[1][0], ap1, bp0, acc2[1][0]);
            FMA2(acc2[1][1], ap1, bp1, acc2[1][1]);
            FMA2(acc2[1][2], ap1, bp2, acc2[1][2]);
            FMA2(acc2[1][3], ap1, bp3, acc2[1][3]);
        }
        __syncthreads();
    }

    float r[4][4];
#pragma unroll
    for (int i = 0; i < 2; i++)
#pragma unroll
        for (int j = 0; j < 4; j++)
            UNPACK2(r[2 * i][j], r[2 * i + 1][j], acc2[i][j]);

    float4 bb4 = *(const float4*)(bias + c * C_DIM + tx * 4);
    float bb[4] = {bb4.x, bb4.y, bb4.z, bb4.w};
    float ss[4];
#pragma unroll
    for (int i = 0; i < 4; i++) {
        float s = 0.f;
#pragma unroll
        for (int j = 0; j < 4; j++) {
            r[i][j] += bb[j];
            s += r[i][j] * r[i][j];
        }
        ss[i] = s;
    }
#pragma unroll
    for (int off = 1; off < 16; off <<= 1)
#pragma unroll
        for (int i = 0; i < 4; i++) ss[i] += __shfl_xor_sync(0xffffffffu, ss[i], off);
    if (tx == 0) {
#pragma unroll
        for (int i = 0; i < 4; i++) s_scale[ty * 4 + i] = rsqrtf(fmaxf(ss[i], 1e-24f));
    }
    __syncthreads();
#pragma unroll
    for (int i = 0; i < 4; i++) {
        float s = s_scale[ty * 4 + i];
        float4 o = make_float4(r[i][0] * s, r[i][1] * s, r[i][2] * s, r[i][3] * s);
        *(float4*)(g_featsA + (size_t)(n0 + ty * 4 + i) * FDIM + c * C_DIM + tx * 4) = o;
    }
}

// ============================================================
// Kernel 3: one iteration. Warp handles TWO nodes (g and g+3072)
// sequentially; grid = 768 blocks -> 5.2 blocks/SM: single wave,
// all warps resident from t=0. Inner loop = round-6 (4-way ILP,
// 5 shfls/edge, guard-free via sentinel padding).
// ============================================================
__global__ __launch_bounds__(128) void iterate_kernel(int pass, float* __restrict__ d_final) {
    const float* __restrict__ src = (pass == 1) ? g_featsB : g_featsA;
    float* __restrict__ dst = (pass == 0) ? g_featsB : (pass == 1) ? g_featsA : d_final;

    const int w = threadIdx.x >> 5, lane = threadIdx.x & 31;
    const int gw = blockIdx.x * 4 + w;   // global warp id in [0, 3072)

#pragma unroll 1
    for (int rep = 0; rep < 2; rep++) {
        const int n = gw + rep * 3072;

        const float* xrow = src + (size_t)n * FDIM + lane * 8;
        float4 x0 = *(const float4*)xrow;
        float4 x1 = *(const float4*)(xrow + 4);
        float4 a0 = make_float4(0.f, 0.f, 0.f, 0.f);
        float4 a1 = make_float4(0.f, 0.f, 0.f, 0.f);

        const int dp = g_deg[n];             // padded to multiple of 4
        const int* erow = g_ell + (size_t)n * CAP;

        for (int i = 0; i < dp; i += 4) {
            int col[4];
#pragma unroll
            for (int j = 0; j < 4; j++) col[j] = __ldg(erow + i + j);

            float4 y0[4], y1[4];
#pragma unroll
            for (int j = 0; j < 4; j++) {
                const float* yr = src + (size_t)col[j] * FDIM + lane * 8;
                y0[j] = *(const float4*)yr;
                y1[j] = *(const float4*)(yr + 4);
            }

            float p[4];
#pragma unroll
            for (int j = 0; j < 4; j++)
                p[j] = x0.x * y0[j].x + x0.y * y0[j].y + x0.z * y0[j].z + x0.w * y0[j].w +
                       x1.x * y1[j].x + x1.y * y1[j].y + x1.z * y1[j].z + x1.w * y1[j].w;
#pragma unroll
            for (int j = 0; j < 4; j++) p[j] += __shfl_xor_sync(0xffffffffu, p[j], 1);
#pragma unroll
            for (int j = 0; j < 4; j++) p[j] += __shfl_xor_sync(0xffffffffu, p[j], 2);
#pragma unroll
            for (int j = 0; j < 4; j++) p[j] += __shfl_xor_sync(0xffffffffu, p[j], 4);
            // |p| <= 1 (unit-norm channel rows): no max-shift needed
            float e[4], t[4];
#pragma unroll
            for (int j = 0; j < 4; j++) e[j] = __expf(p[j]);
#pragma unroll
            for (int j = 0; j < 4; j++) t[j] = e[j] + __shfl_xor_sync(0xffffffffu, e[j], 8);
#pragma unroll
            for (int j = 0; j < 4; j++) t[j] += __shfl_xor_sync(0xffffffffu, t[j], 16);
#pragma unroll
            for (int j = 0; j < 4; j++) {
                float wgt = __fdividef(e[j], t[j]);
                a0.x += wgt * y0[j].x; a0.y += wgt * y0[j].y;
                a0.z += wgt * y0[j].z; a0.w += wgt * y0[j].w;
                a1.x += wgt * y1[j].x; a1.y += wgt * y1[j].y;
                a1.z += wgt * y1[j].z; a1.w += wgt * y1[j].w;
            }
        }

        // self + aggregate, per-channel (8-lane group) L2 norm
        float v[8];
        v[0] = x0.x + a0.x; v[1] = x0.y + a0.y; v[2] = x0.z + a0.z; v[3] = x0.w + a0.w;
        v[4] = x1.x + a1.x; v[5] = x1.y + a1.y; v[6] = x1.z + a1.z; v[7] = x1.w + a1.w;
        float sq = 0.f;
#pragma unroll
        for (int k = 0; k < 8; k++) sq += v[k] * v[k];
        sq += __shfl_xor_sync(0xffffffffu, sq, 1);
        sq += __shfl_xor_sync(0xffffffffu, sq, 2);
        sq += __shfl_xor_sync(0xffffffffu, sq, 4);
        float sc = rsqrtf(fmaxf(sq, 1e-24f));
        float* drow = dst + (size_t)n * FDIM + lane * 8;
        *(float4*)drow       = make_float4(v[0] * sc, v[1] * sc, v[2] * sc, v[3] * sc);
        *(float4*)(drow + 4) = make_float4(v[4] * sc, v[5] * sc, v[6] * sc, v[7] * sc);
    }
}

// ============================================================
extern "C" void kernel_launch(void* const* d_in, const int* in_sizes, int n_in,
                              void* d_out, int out_size) {
    const float* features = (const float*)d_in[0];   // [6144, 512]
    const int*   adj      = (const int*)d_in[1];     // [6144, 6144]
    const float* W        = (const float*)d_in[2];   // [4, 512, 64]
    const float* b        = (const float*)d_in[3];   // [4, 1, 64]
    float* out = (float*)d_out;                      // [6144, 256]

    build_ell_kernel<<<NN / 8, 256>>>(adj);
    project_kernel<<<dim3(NN / 64, CHANNELS), 256>>>(features, W, b);
    iterate_kernel<<<768, 128>>>(0, out);
    iterate_kernel<<<768, 128>>>(1, out);
    iterate_kernel<<<768, 128>>>(2, out);
}